// round 3
// baseline (speedup 1.0000x reference)
#include <cuda_runtime.h>
#include <math.h>

#define DS 260
#define SMEM_BYTES 232448

typedef unsigned long long u64t;
#define A_COMP(a,u) ((u)==0?(a).x:(u)==1?(a).y:(u)==2?(a).z:(a).w)

__device__ __forceinline__ u64t pack2(float lo, float hi) {
    u64t r; asm("mov.b64 %0,{%1,%2};" : "=l"(r) : "f"(lo), "f"(hi)); return r;
}
__device__ __forceinline__ void fma2(u64t& d, u64t a, u64t b) {
    asm("fma.rn.f32x2 %0,%1,%2,%0;" : "+l"(d) : "l"(a), "l"(b));
}
__device__ __forceinline__ float2 unpack2(u64t v) {
    float lo, hi; asm("mov.b64 {%0,%1},%2;" : "=f"(lo), "=f"(hi) : "l"(v));
    return make_float2(lo, hi);
}
__device__ __forceinline__ float gelu_f(float v) {
    return 0.5f * v * (1.0f + erff(v * 0.70710678118654752f));
}

// LayerNorm over 64 rows x 256 cols (stride DS). 4 threads/row, 64-col segments.
// Safe in-place (cross-thread data only via shfl).
__device__ void ln_rows(const float* src, float* dst,
                        const float* __restrict__ g, const float* __restrict__ bv, int tid) {
    const int t = tid >> 2, qq = tid & 3;
    const float* row = src + t * DS + qq * 64;
    float s = 0.f, s2 = 0.f;
#pragma unroll
    for (int c = 0; c < 64; c += 4) {
        float4 v = *(const float4*)(row + c);
        s += (v.x + v.y) + (v.z + v.w);
        s2 += v.x * v.x + v.y * v.y + v.z * v.z + v.w * v.w;
    }
    s  += __shfl_xor_sync(~0u, s, 1);  s2 += __shfl_xor_sync(~0u, s2, 1);
    s  += __shfl_xor_sync(~0u, s, 2);  s2 += __shfl_xor_sync(~0u, s2, 2);
    const float mean = s * (1.0f / 256.0f);
    const float rs = rsqrtf(s2 * (1.0f / 256.0f) - mean * mean + 1e-5f);
    float* drow = dst + t * DS + qq * 64;
#pragma unroll
    for (int c = 0; c < 64; c += 4) {
        float4 v = *(const float4*)(row + c);
        float4 gv = *(const float4*)(g + qq * 64 + c);
        float4 bb = *(const float4*)(bv + qq * 64 + c);
        float4 o;
        o.x = (v.x - mean) * rs * gv.x + bb.x;
        o.y = (v.y - mean) * rs * gv.y + bb.y;
        o.z = (v.z - mean) * rs * gv.z + bb.z;
        o.w = (v.w - mean) * rs * gv.w + bb.w;
        *(float4*)(drow + c) = o;
    }
}

// acc[8][4] (f32x2: cols m*64+l and m*64+32+l) += A[8 rows x 32] @ slab[32 x 256]
__device__ __forceinline__ void mac256(const float* A, int sa, int a0, const float* slab,
                                       u64t acc[8][4], int r0, int l) {
#pragma unroll
    for (int kk = 0; kk < 32; kk += 4) {
        float4 a4[8];
#pragma unroll
        for (int i = 0; i < 8; i++) a4[i] = *(const float4*)(A + (r0 + i) * sa + a0 + kk);
#pragma unroll
        for (int u = 0; u < 4; u++) {
            u64t bp[4];
#pragma unroll
            for (int m = 0; m < 4; m++)
                bp[m] = pack2(slab[(kk + u) * 256 + m * 64 + l],
                              slab[(kk + u) * 256 + m * 64 + 32 + l]);
#pragma unroll
            for (int i = 0; i < 8; i++) {
                float av = A_COMP(a4[i], u);
                u64t ap = pack2(av, av);
#pragma unroll
                for (int m = 0; m < 4; m++) fma2(acc[i][m], ap, bp[m]);
            }
        }
    }
}

// stage 32x256 fp32 from global (row stride gs) into slab
__device__ __forceinline__ void stage32(const float* g, int gs, float* slab, int tid) {
    for (int id = tid; id < 2048; id += 256) {
        int kk = id >> 6, c = (id & 63) << 2;
        *(float4*)(slab + kk * 256 + c) = *(const float4*)(g + kk * gs + c);
    }
}

__global__ void __launch_bounds__(256, 1)
block_attn_kernel(const float* __restrict__ x,
                  const float* __restrict__ ln1_g, const float* __restrict__ ln1_b,
                  const float* __restrict__ ln2_g, const float* __restrict__ ln2_b,
                  const float* __restrict__ w_qkv, const float* __restrict__ w_out,
                  const float* __restrict__ rpb,
                  const float* __restrict__ ln3_g, const float* __restrict__ ln3_b,
                  const float* __restrict__ w1, const float* __restrict__ pb1,
                  const float* __restrict__ w2, const float* __restrict__ pb2,
                  float* __restrict__ outp) {
    extern __shared__ float sm[];
    float* sT   = sm;                 // 64 x DS : LN output (GEMM A operand)
    float* sAcc = sm + 16640;         // 64 x DS : residual accumulator
    float* sH   = sm + 33280;         // 64 x DS : FFN hidden / attn scratch overlay
    float* slab = sm + 49920;         // 8192 : weight slab

    float* q_s   = sH;                // 64 x 36
    float* v_s   = sH + 2304;         // 64 x 36
    float* kT_s  = sH + 4608;         // 32 x 65
    float* o_s   = sH + 6688;         // 64 x 36
    float* rpb_s = sH + 8992;         // 225 x 8
    float* sim_s = sH + 10792;        // 64 x 68

    const int tid = threadIdx.x;
    const int l = tid & 31;
    const int r0 = (tid >> 5) << 3;

    const int win = blockIdx.x;
    const int bb = win >> 10, rem = win & 1023, xx = rem >> 5, yy = rem & 31;
    const int base_g = bb * 16777216 + xx * 2048 + yy * 8;

    // S0: load x window -> sAcc[token][dim], token = w1r*8 + w2c
    for (int id = tid; id < 4096; id += 256) {
        int dd = id >> 4, w1r = (id >> 1) & 7, half = id & 1;
        float4 v = *(const float4*)(x + base_g + dd * 65536 + w1r * 256 + half * 4);
        int t0 = w1r * 8 + half * 4;
        sAcc[(t0 + 0) * DS + dd] = v.x; sAcc[(t0 + 1) * DS + dd] = v.y;
        sAcc[(t0 + 2) * DS + dd] = v.z; sAcc[(t0 + 3) * DS + dd] = v.w;
    }
    __syncthreads();

    // S1: double LayerNorm (faithful to reference)
    ln_rows(sAcc, sT, ln1_g, ln1_b, tid);
    ln_rows(sT, sT, ln2_g, ln2_b, tid);
    __syncthreads();
    for (int id = tid; id < 16384; id += 256) sAcc[(id >> 8) * DS + (id & 255)] = 0.f;
    for (int id = tid; id < 1800; id += 256) rpb_s[id] = rpb[id];
    __syncthreads();

    const float qscale = 0.17677669529663687f;

    // S2: attention, per head
#pragma unroll 1
    for (int h = 0; h < 8; h++) {
        u64t aqk[8]; float av2[8];
#pragma unroll
        for (int i = 0; i < 8; i++) { aqk[i] = 0ull; av2[i] = 0.f; }
#pragma unroll 1
        for (int kt = 0; kt < 4; kt++) {
            for (int id = tid; id < 6144; id += 256) {
                int kk = id / 96, c = id - kk * 96;
                slab[id] = w_qkv[(kt * 64 + kk) * 768 + (c >> 5) * 256 + h * 32 + (c & 31)];
            }
            __syncthreads();
#pragma unroll 2
            for (int kk = 0; kk < 64; kk += 4) {
                float4 a4[8];
#pragma unroll
                for (int i = 0; i < 8; i++)
                    a4[i] = *(const float4*)(sT + (r0 + i) * DS + kt * 64 + kk);
#pragma unroll
                for (int u = 0; u < 4; u++) {
                    float bq = slab[(kk + u) * 96 + l];
                    float bk = slab[(kk + u) * 96 + 32 + l];
                    float bvv = slab[(kk + u) * 96 + 64 + l];
                    u64t bqk = pack2(bq, bk);
#pragma unroll
                    for (int i = 0; i < 8; i++) {
                        float av = A_COMP(a4[i], u);
                        fma2(aqk[i], pack2(av, av), bqk);
                        av2[i] = fmaf(av, bvv, av2[i]);
                    }
                }
            }
            __syncthreads();
        }
#pragma unroll
        for (int i = 0; i < 8; i++) {
            float2 qk = unpack2(aqk[i]);
            q_s[(r0 + i) * 36 + l] = qk.x * qscale;
            kT_s[l * 65 + (r0 + i)] = qk.y;
            v_s[(r0 + i) * 36 + l] = av2[i];
        }
        __syncthreads();

        // sim = q @ kT + bias
        u64t sacc[8];
#pragma unroll
        for (int i = 0; i < 8; i++) sacc[i] = 0ull;
#pragma unroll
        for (int kk = 0; kk < 32; kk += 4) {
            float4 a4[8];
#pragma unroll
            for (int i = 0; i < 8; i++) a4[i] = *(const float4*)(q_s + (r0 + i) * 36 + kk);
#pragma unroll
            for (int u = 0; u < 4; u++) {
                u64t bj = pack2(kT_s[(kk + u) * 65 + l], kT_s[(kk + u) * 65 + 32 + l]);
#pragma unroll
                for (int i = 0; i < 8; i++) {
                    float av = A_COMP(a4[i], u);
                    fma2(sacc[i], pack2(av, av), bj);
                }
            }
        }
#pragma unroll
        for (int i = 0; i < 8; i++) {
            int ti = r0 + i;
            float2 sv = unpack2(sacc[i]);
            int j = l, d0 = (ti >> 3) - (j >> 3) + 7, d1 = (ti & 7) - (j & 7) + 7;
            sim_s[ti * 68 + j] = sv.x + rpb_s[(d0 * 15 + d1) * 8 + h];
            j = l + 32; d0 = (ti >> 3) - (j >> 3) + 7; d1 = (ti & 7) - (j & 7) + 7;
            sim_s[ti * 68 + j] = sv.y + rpb_s[(d0 * 15 + d1) * 8 + h];
        }
        __syncthreads();

        // softmax: 4 threads/row, 16 cols each
        {
            int t = tid >> 2, qq = tid & 3;
            float* srow = sim_s + t * 68 + qq * 16;
            float vv[16], m = -1e30f;
#pragma unroll
            for (int c = 0; c < 16; c++) { vv[c] = srow[c]; m = fmaxf(m, vv[c]); }
            m = fmaxf(m, __shfl_xor_sync(~0u, m, 1));
            m = fmaxf(m, __shfl_xor_sync(~0u, m, 2));
            float ss = 0.f;
#pragma unroll
            for (int c = 0; c < 16; c++) { vv[c] = __expf(vv[c] - m); ss += vv[c]; }
            ss += __shfl_xor_sync(~0u, ss, 1);
            ss += __shfl_xor_sync(~0u, ss, 2);
            float inv = 1.0f / ss;
#pragma unroll
            for (int c = 0; c < 16; c++) srow[c] = vv[c] * inv;
        }
        __syncthreads();

        // o = P @ v  (row pairs packed)
        u64t pacc[4];
#pragma unroll
        for (int i = 0; i < 4; i++) pacc[i] = 0ull;
#pragma unroll
        for (int jj = 0; jj < 64; jj += 4) {
            float4 a4[8];
#pragma unroll
            for (int i = 0; i < 8; i++) a4[i] = *(const float4*)(sim_s + (r0 + i) * 68 + jj);
#pragma unroll
            for (int u = 0; u < 4; u++) {
                float bvv = v_s[(jj + u) * 36 + l];
                u64t bp = pack2(bvv, bvv);
#pragma unroll
                for (int i = 0; i < 4; i++)
                    fma2(pacc[i], pack2(A_COMP(a4[2 * i], u), A_COMP(a4[2 * i + 1], u)), bp);
            }
        }
#pragma unroll
        for (int i = 0; i < 4; i++) {
            float2 ov = unpack2(pacc[i]);
            o_s[(r0 + 2 * i) * 36 + l] = ov.x;
            o_s[(r0 + 2 * i + 1) * 36 + l] = ov.y;
        }
        __syncthreads();

        // sAcc += o @ w_out[h*32 : h*32+32, :]
        stage32(w_out + h * 32 * 256, 256, slab, tid);
        __syncthreads();
        u64t acc[8][4];
#pragma unroll
        for (int i = 0; i < 8; i++)
#pragma unroll
            for (int m = 0; m < 4; m++) acc[i][m] = 0ull;
        mac256(o_s, 36, 0, slab, acc, r0, l);
#pragma unroll
        for (int i = 0; i < 8; i++)
#pragma unroll
            for (int m = 0; m < 4; m++) {
                float2 f = unpack2(acc[i][m]);
                sAcc[(r0 + i) * DS + m * 64 + l] += f.x;
                sAcc[(r0 + i) * DS + m * 64 + 32 + l] += f.y;
            }
        __syncthreads();
    }

    // S3: residual (reload x)
    for (int id = tid; id < 4096; id += 256) {
        int dd = id >> 4, w1r = (id >> 1) & 7, half = id & 1;
        float4 v = *(const float4*)(x + base_g + dd * 65536 + w1r * 256 + half * 4);
        int t0 = w1r * 8 + half * 4;
        sAcc[(t0 + 0) * DS + dd] += v.x; sAcc[(t0 + 1) * DS + dd] += v.y;
        sAcc[(t0 + 2) * DS + dd] += v.z; sAcc[(t0 + 3) * DS + dd] += v.w;
    }
    __syncthreads();

    // S4: LN3
    ln_rows(sAcc, sT, ln3_g, ln3_b, tid);
    __syncthreads();

    // S5: FFN, 4 chunks of 256 hidden cols
#pragma unroll 1
    for (int fc = 0; fc < 4; fc++) {
        u64t acc[8][4];
#pragma unroll
        for (int i = 0; i < 8; i++)
#pragma unroll
            for (int m = 0; m < 4; m++) acc[i][m] = 0ull;
#pragma unroll 1
        for (int kt = 0; kt < 8; kt++) {
            stage32(w1 + (kt * 32) * 1024 + fc * 256, 1024, slab, tid);
            __syncthreads();
            mac256(sT, DS, kt * 32, slab, acc, r0, l);
            __syncthreads();
        }
#pragma unroll
        for (int i = 0; i < 8; i++)
#pragma unroll
            for (int m = 0; m < 4; m++) {
                float2 f = unpack2(acc[i][m]);
                int c0 = m * 64 + l, c1 = c0 + 32;
                sH[(r0 + i) * DS + c0] = gelu_f(f.x + pb1[fc * 256 + c0]);
                sH[(r0 + i) * DS + c1] = gelu_f(f.y + pb1[fc * 256 + c1]);
            }
        __syncthreads();

        u64t acc2[8][4];
#pragma unroll
        for (int i = 0; i < 8; i++)
#pragma unroll
            for (int m = 0; m < 4; m++) acc2[i][m] = 0ull;
#pragma unroll 1
        for (int kt = 0; kt < 8; kt++) {
            stage32(w2 + (fc * 256 + kt * 32) * 256, 256, slab, tid);
            __syncthreads();
            mac256(sH, DS, kt * 32, slab, acc2, r0, l);
            __syncthreads();
        }
#pragma unroll
        for (int i = 0; i < 8; i++)
#pragma unroll
            for (int m = 0; m < 4; m++) {
                float2 f = unpack2(acc2[i][m]);
                sAcc[(r0 + i) * DS + m * 64 + l] += f.x;
                sAcc[(r0 + i) * DS + m * 64 + 32 + l] += f.y;
            }
        __syncthreads();
    }

    // S6: store (+ b2), transposed back to (b, d, H, W)
    for (int id = tid; id < 4096; id += 256) {
        int dd = id >> 4, w1r = (id >> 1) & 7, half = id & 1;
        int t0 = w1r * 8 + half * 4;
        float bb2 = pb2[dd];
        float4 o;
        o.x = sAcc[(t0 + 0) * DS + dd] + bb2;
        o.y = sAcc[(t0 + 1) * DS + dd] + bb2;
        o.z = sAcc[(t0 + 2) * DS + dd] + bb2;
        o.w = sAcc[(t0 + 3) * DS + dd] + bb2;
        *(float4*)(outp + base_g + dd * 65536 + w1r * 256 + half * 4) = o;
    }
}

extern "C" void kernel_launch(void* const* d_in, const int* in_sizes, int n_in,
                              void* d_out, int out_size) {
    cudaFuncSetAttribute(block_attn_kernel,
                         cudaFuncAttributeMaxDynamicSharedMemorySize, SMEM_BYTES);
    block_attn_kernel<<<2048, 256, SMEM_BYTES>>>(
        (const float*)d_in[0], (const float*)d_in[1], (const float*)d_in[2],
        (const float*)d_in[3], (const float*)d_in[4], (const float*)d_in[5],
        (const float*)d_in[6], (const float*)d_in[7], (const float*)d_in[8],
        (const float*)d_in[9], (const float*)d_in[10], (const float*)d_in[11],
        (const float*)d_in[12], (const float*)d_in[13], (float*)d_out);
}

// round 5
// speedup vs baseline: 1.7115x; 1.7115x over previous
#include <cuda_runtime.h>
#include <math.h>
#include <stdint.h>

#define DS 260        // stride for sT / sAcc (mod 32 == 4 -> conflict-free frags)
#define HS 258        // stride for sH
#define SLS 260       // slab stride (256-col stages)
#define QSL 100       // slab stride (96-col qkv stages)
#define SMEM_BYTES 232448

// float offsets: sT[0,16640) | R2 scratch/sAcc [16640,33280) | sH [33280,49792) | slab [49792,58112)
#define OFF_R2 16640
#define OFF_H 33280
#define OFF_SLAB 49792

typedef unsigned long long u64t;
#define A_COMP(a,u) ((u)==0?(a).x:(u)==1?(a).y:(u)==2?(a).z:(a).w)

__device__ __forceinline__ u64t pack2(float lo, float hi) {
    u64t r; asm("mov.b64 %0,{%1,%2};" : "=l"(r) : "f"(lo), "f"(hi)); return r;
}
__device__ __forceinline__ void fma2(u64t& d, u64t a, u64t b) {
    asm("fma.rn.f32x2 %0,%1,%2,%0;" : "+l"(d) : "l"(a), "l"(b));
}
__device__ __forceinline__ float2 unpack2(u64t v) {
    float lo, hi; asm("mov.b64 {%0,%1},%2;" : "=f"(lo), "=f"(hi) : "l"(v));
    return make_float2(lo, hi);
}
__device__ __forceinline__ float gelu_f(float v) {
    return 0.5f * v * (1.0f + erff(v * 0.70710678118654752f));
}
__device__ __forceinline__ uint32_t tf32_bits(float x) {
    uint32_t r; asm("cvt.rna.tf32.f32 %0, %1;" : "=r"(r) : "f"(x)); return r;
}
__device__ __forceinline__ void mma8(float c[4], const uint32_t a[4], uint32_t b0, uint32_t b1) {
    asm volatile("mma.sync.aligned.m16n8k8.row.col.f32.tf32.tf32.f32 "
        "{%0,%1,%2,%3},{%4,%5,%6,%7},{%8,%9},{%0,%1,%2,%3};"
        : "+f"(c[0]), "+f"(c[1]), "+f"(c[2]), "+f"(c[3])
        : "r"(a[0]), "r"(a[1]), "r"(a[2]), "r"(a[3]), "r"(b0), "r"(b1));
}

// LayerNorm: 64 rows x 256 cols, stride DS. 4 threads/row. In-place safe.
__device__ void ln_rows(const float* src, float* dst,
                        const float* __restrict__ g, const float* __restrict__ bv, int tid) {
    const int t = tid >> 2, qq = tid & 3;
    const float* row = src + t * DS + qq * 64;
    float s = 0.f, s2 = 0.f;
#pragma unroll
    for (int c = 0; c < 64; c += 4) {
        float4 v = *(const float4*)(row + c);
        s += (v.x + v.y) + (v.z + v.w);
        s2 += v.x * v.x + v.y * v.y + v.z * v.z + v.w * v.w;
    }
    s  += __shfl_xor_sync(~0u, s, 1);  s2 += __shfl_xor_sync(~0u, s2, 1);
    s  += __shfl_xor_sync(~0u, s, 2);  s2 += __shfl_xor_sync(~0u, s2, 2);
    const float mean = s * (1.0f / 256.0f);
    const float rs = rsqrtf(s2 * (1.0f / 256.0f) - mean * mean + 1e-5f);
    float* drow = dst + t * DS + qq * 64;
#pragma unroll
    for (int c = 0; c < 64; c += 4) {
        float4 v = *(const float4*)(row + c);
        float4 gv = *(const float4*)(g + qq * 64 + c);
        float4 bb = *(const float4*)(bv + qq * 64 + c);
        float4 o;
        o.x = (v.x - mean) * rs * gv.x + bb.x;
        o.y = (v.y - mean) * rs * gv.y + bb.y;
        o.z = (v.z - mean) * rs * gv.z + bb.z;
        o.w = (v.w - mean) * rs * gv.w + bb.w;
        *(float4*)(drow + c) = o;
    }
}

// Warp GEMM over one 32-deep K chunk. acc[2*NT][4]: mt-major then nt.
// Warp (wr,wc): rows wr*32 + {0,16}+..., cols wc*(NT*8) + nt*8 + ...
template<int NT>
__device__ __forceinline__ void wgemm32(const float* __restrict__ A, int as, int acol0,
                                        const float* __restrict__ Bs, int bs,
                                        float (*acc)[4], int wr, int wc, int g, int t) {
    const int r0 = wr * 32 + g;
    const int nb = wc * (NT * 8) + g;
#pragma unroll
    for (int k8 = 0; k8 < 4; k8++) {
        const int c0 = acol0 + k8 * 8 + t;
        uint32_t a0[4], a1[4];
        a0[0] = tf32_bits(A[(r0)      * as + c0]);
        a0[1] = tf32_bits(A[(r0 + 8)  * as + c0]);
        a0[2] = tf32_bits(A[(r0)      * as + c0 + 4]);
        a0[3] = tf32_bits(A[(r0 + 8)  * as + c0 + 4]);
        a1[0] = tf32_bits(A[(r0 + 16) * as + c0]);
        a1[1] = tf32_bits(A[(r0 + 24) * as + c0]);
        a1[2] = tf32_bits(A[(r0 + 16) * as + c0 + 4]);
        a1[3] = tf32_bits(A[(r0 + 24) * as + c0 + 4]);
        const float* B0 = Bs + (k8 * 8 + t) * bs;
        const float* B1 = Bs + (k8 * 8 + t + 4) * bs;
#pragma unroll
        for (int nt = 0; nt < NT; nt++) {
            uint32_t b0 = __float_as_uint(B0[nb + nt * 8]);
            uint32_t b1 = __float_as_uint(B1[nb + nt * 8]);
            mma8(acc[nt], a0, b0, b1);
            mma8(acc[NT + nt], a1, b0, b1);
        }
    }
}

// stage 32x256 fp32 (row stride gs) -> slab (stride SLS), tf32-rounded
__device__ __forceinline__ void stage256(const float* __restrict__ gp, int gs, float* s, int tid) {
    for (int id = tid; id < 2048; id += 256) {
        int kk = id >> 6, c = (id & 63) << 2;
        float4 v = *(const float4*)(gp + kk * gs + c);
        float* d = s + kk * SLS + c;
        d[0] = __uint_as_float(tf32_bits(v.x));
        d[1] = __uint_as_float(tf32_bits(v.y));
        d[2] = __uint_as_float(tf32_bits(v.z));
        d[3] = __uint_as_float(tf32_bits(v.w));
    }
}

// stage 32x96 qkv slice for head h, k-chunk kt: slab cols 0-31=q,32-63=k,64-95=v
__device__ __forceinline__ void stage_qkv(const float* __restrict__ wq, int h, int kt,
                                          float* s, int tid) {
    for (int id = tid; id < 768; id += 256) {
        int kk = id / 24, c4 = (id % 24) * 4;
        const float* gr = wq + (kt * 32 + kk) * 768 + (c4 >> 5) * 256 + h * 32 + (c4 & 31);
        float4 v = *(const float4*)gr;
        float* d = s + kk * QSL + c4;
        d[0] = __uint_as_float(tf32_bits(v.x));
        d[1] = __uint_as_float(tf32_bits(v.y));
        d[2] = __uint_as_float(tf32_bits(v.z));
        d[3] = __uint_as_float(tf32_bits(v.w));
    }
}

__global__ void __launch_bounds__(256, 1)
block_attn_kernel(const float* __restrict__ x,
                  const float* __restrict__ ln1_g, const float* __restrict__ ln1_b,
                  const float* __restrict__ ln2_g, const float* __restrict__ ln2_b,
                  const float* __restrict__ w_qkv, const float* __restrict__ w_out,
                  const float* __restrict__ rpb,
                  const float* __restrict__ ln3_g, const float* __restrict__ ln3_b,
                  const float* __restrict__ w1, const float* __restrict__ pb1,
                  const float* __restrict__ w2, const float* __restrict__ pb2,
                  float* __restrict__ outp) {
    extern __shared__ float sm[];
    float* sT   = sm;               // LN output (GEMM A operand)
    float* sR2  = sm + OFF_R2;      // x-stage / attn scratch / sAcc
    float* sH   = sm + OFF_H;       // FFN hidden (stride HS)
    float* slab = sm + OFF_SLAB;    // weight slab

    // attn scratch overlay inside sR2
    float* q_s   = sR2;             // 64 x 36
    float* v_s   = sR2 + 2304;      // 64 x 36
    float* kT_s  = sR2 + 4608;      // 32 x 65
    float* o_s   = sR2 + 6688;      // 64 x 36
    float* rpb_s = sR2 + 8992;      // 225 x 8
    float* sim_s = sR2 + 10792;     // 64 x 68
    float* sAcc  = sR2;             // after attention: 64 x DS residual accum

    const int tid = threadIdx.x;
    const int l = tid & 31;
    const int wid = tid >> 5;
    const int r0s = wid << 3;       // fp32 attn row base (8 rows/warp)
    const int wr = wid >> 2, wc = wid & 3;   // tensor warp grid 2x4
    const int g = l >> 2, t = l & 3;         // mma lane coords

    const int win = blockIdx.x;
    const int bb = win >> 10, rem = win & 1023, xx = rem >> 5, yy = rem & 31;
    const int base_g = bb * 16777216 + xx * 2048 + yy * 8;

    // S0: x window -> sR2[token][dim]
    for (int id = tid; id < 4096; id += 256) {
        int dd = id >> 4, w1r = (id >> 1) & 7, half = id & 1;
        float4 v = *(const float4*)(x + base_g + dd * 65536 + w1r * 256 + half * 4);
        int t0 = w1r * 8 + half * 4;
        sR2[(t0 + 0) * DS + dd] = v.x; sR2[(t0 + 1) * DS + dd] = v.y;
        sR2[(t0 + 2) * DS + dd] = v.z; sR2[(t0 + 3) * DS + dd] = v.w;
    }
    __syncthreads();

    // S1: double LN -> sT
    ln_rows(sR2, sT, ln1_g, ln1_b, tid);
    ln_rows(sT, sT, ln2_g, ln2_b, tid);
    __syncthreads();
    for (int id = tid; id < 1800; id += 256) rpb_s[id] = rpb[id];
    __syncthreads();

    const float qscale = 0.17677669529663687f;

    // projection accumulator held in registers across heads
    float pacc[16][4];
#pragma unroll
    for (int i = 0; i < 16; i++)
#pragma unroll
        for (int e = 0; e < 4; e++) pacc[i][e] = 0.f;

    // S2: per-head attention
#pragma unroll 1
    for (int h = 0; h < 8; h++) {
        // QKV tensor GEMM: [64x256] @ [256x96]
        float qacc[6][4];
#pragma unroll
        for (int i = 0; i < 6; i++)
#pragma unroll
            for (int e = 0; e < 4; e++) qacc[i][e] = 0.f;
#pragma unroll 1
        for (int kt = 0; kt < 8; kt++) {
            stage_qkv(w_qkv, h, kt, slab, tid);
            __syncthreads();
            wgemm32<3>(sT, DS, kt * 32, slab, QSL, qacc, wr, wc, g, t);
            __syncthreads();
        }
        // scatter q/k/v fragments
#pragma unroll
        for (int mt = 0; mt < 2; mt++)
#pragma unroll
            for (int nt = 0; nt < 3; nt++)
#pragma unroll
                for (int e = 0; e < 4; e++) {
                    int row = wr * 32 + mt * 16 + g + ((e >> 1) << 3);
                    int col = wc * 24 + nt * 8 + 2 * t + (e & 1);
                    float vv = qacc[mt * 3 + nt][e];
                    if (col < 32)       q_s[row * 36 + col] = vv * qscale;
                    else if (col < 64)  kT_s[(col - 32) * 65 + row] = vv;
                    else                v_s[row * 36 + (col - 64)] = vv;
                }
        __syncthreads();

        // sim = q @ kT + bias (fp32 f32x2)
        u64t sacc[8];
#pragma unroll
        for (int i = 0; i < 8; i++) sacc[i] = 0ull;
#pragma unroll
        for (int kk = 0; kk < 32; kk += 4) {
            float4 a4[8];
#pragma unroll
            for (int i = 0; i < 8; i++) a4[i] = *(const float4*)(q_s + (r0s + i) * 36 + kk);
#pragma unroll
            for (int u = 0; u < 4; u++) {
                u64t bj = pack2(kT_s[(kk + u) * 65 + l], kT_s[(kk + u) * 65 + 32 + l]);
#pragma unroll
                for (int i = 0; i < 8; i++) {
                    float av = A_COMP(a4[i], u);
                    fma2(sacc[i], pack2(av, av), bj);
                }
            }
        }
#pragma unroll
        for (int i = 0; i < 8; i++) {
            int ti = r0s + i;
            float2 sv = unpack2(sacc[i]);
            int j = l, d0 = (ti >> 3) - (j >> 3) + 7, d1 = (ti & 7) - (j & 7) + 7;
            sim_s[ti * 68 + j] = sv.x + rpb_s[(d0 * 15 + d1) * 8 + h];
            j = l + 32; d0 = (ti >> 3) - (j >> 3) + 7; d1 = (ti & 7) - (j & 7) + 7;
            sim_s[ti * 68 + j] = sv.y + rpb_s[(d0 * 15 + d1) * 8 + h];
        }
        __syncthreads();

        // softmax: 4 threads/row
        {
            int tr = tid >> 2, qq = tid & 3;
            float* srow = sim_s + tr * 68 + qq * 16;
            float vv[16], m = -1e30f;
#pragma unroll
            for (int c = 0; c < 16; c++) { vv[c] = srow[c]; m = fmaxf(m, vv[c]); }
            m = fmaxf(m, __shfl_xor_sync(~0u, m, 1));
            m = fmaxf(m, __shfl_xor_sync(~0u, m, 2));
            float ss = 0.f;
#pragma unroll
            for (int c = 0; c < 16; c++) { vv[c] = __expf(vv[c] - m); ss += vv[c]; }
            ss += __shfl_xor_sync(~0u, ss, 1);
            ss += __shfl_xor_sync(~0u, ss, 2);
            float inv = 1.0f / ss;
#pragma unroll
            for (int c = 0; c < 16; c++) srow[c] = vv[c] * inv;
        }
        __syncthreads();

        // o = P @ v (fp32)
        u64t pv[4];
#pragma unroll
        for (int i = 0; i < 4; i++) pv[i] = 0ull;
#pragma unroll
        for (int jj = 0; jj < 64; jj += 4) {
            float4 a4[8];
#pragma unroll
            for (int i = 0; i < 8; i++) a4[i] = *(const float4*)(sim_s + (r0s + i) * 68 + jj);
#pragma unroll
            for (int u = 0; u < 4; u++) {
                float bvv = v_s[(jj + u) * 36 + l];
                u64t bp = pack2(bvv, bvv);
#pragma unroll
                for (int i = 0; i < 4; i++)
                    fma2(pv[i], pack2(A_COMP(a4[2 * i], u), A_COMP(a4[2 * i + 1], u)), bp);
            }
        }
#pragma unroll
        for (int i = 0; i < 4; i++) {
            float2 ov = unpack2(pv[i]);
            o_s[(r0s + 2 * i) * 36 + l]     = ov.x;
            o_s[(r0s + 2 * i + 1) * 36 + l] = ov.y;
        }
        // stage w_out slice; sync orders both o_s and slab
        stage256(w_out + h * 32 * 256, 256, slab, tid);
        __syncthreads();
        wgemm32<8>(o_s, 36, 0, slab, SLS, pacc, wr, wc, g, t);
        __syncthreads();
    }

    // S3: sAcc = proj (frag scatter) ...
#pragma unroll
    for (int mt = 0; mt < 2; mt++)
#pragma unroll
        for (int nt = 0; nt < 8; nt++)
#pragma unroll
            for (int e = 0; e < 4; e++) {
                int row = wr * 32 + mt * 16 + g + ((e >> 1) << 3);
                int col = wc * 64 + nt * 8 + 2 * t + (e & 1);
                sAcc[row * DS + col] = pacc[mt * 8 + nt][e];
            }
    __syncthreads();
    // ... + x (residual)
    for (int id = tid; id < 4096; id += 256) {
        int dd = id >> 4, w1r = (id >> 1) & 7, half = id & 1;
        float4 v = *(const float4*)(x + base_g + dd * 65536 + w1r * 256 + half * 4);
        int t0 = w1r * 8 + half * 4;
        sAcc[(t0 + 0) * DS + dd] += v.x; sAcc[(t0 + 1) * DS + dd] += v.y;
        sAcc[(t0 + 2) * DS + dd] += v.z; sAcc[(t0 + 3) * DS + dd] += v.w;
    }
    __syncthreads();

    // S4: LN3 -> sT
    ln_rows(sAcc, sT, ln3_g, ln3_b, tid);
    __syncthreads();

    // S5: FFN via tensor GEMMs
    float f2acc[16][4];
#pragma unroll
    for (int i = 0; i < 16; i++)
#pragma unroll
        for (int e = 0; e < 4; e++) f2acc[i][e] = 0.f;

#pragma unroll 1
    for (int fc = 0; fc < 4; fc++) {
        float f1acc[16][4];
#pragma unroll
        for (int i = 0; i < 16; i++)
#pragma unroll
            for (int e = 0; e < 4; e++) f1acc[i][e] = 0.f;
#pragma unroll 1
        for (int kt = 0; kt < 8; kt++) {
            stage256(w1 + (kt * 32) * 1024 + fc * 256, 1024, slab, tid);
            __syncthreads();
            wgemm32<8>(sT, DS, kt * 32, slab, SLS, f1acc, wr, wc, g, t);
            __syncthreads();
        }
        // bias + gelu -> sH
#pragma unroll
        for (int mt = 0; mt < 2; mt++)
#pragma unroll
            for (int nt = 0; nt < 8; nt++)
#pragma unroll
                for (int e = 0; e < 4; e++) {
                    int row = wr * 32 + mt * 16 + g + ((e >> 1) << 3);
                    int col = wc * 64 + nt * 8 + 2 * t + (e & 1);
                    sH[row * HS + col] = gelu_f(f1acc[mt * 8 + nt][e] + pb1[fc * 256 + col]);
                }
#pragma unroll 1
        for (int kt = 0; kt < 8; kt++) {
            stage256(w2 + (fc * 256 + kt * 32) * 256, 256, slab, tid);
            __syncthreads();
            wgemm32<8>(sH, HS, kt * 32, slab, SLS, f2acc, wr, wc, g, t);
            __syncthreads();
        }
    }
    // scatter FFN2 into sAcc
#pragma unroll
    for (int mt = 0; mt < 2; mt++)
#pragma unroll
        for (int nt = 0; nt < 8; nt++)
#pragma unroll
            for (int e = 0; e < 4; e++) {
                int row = wr * 32 + mt * 16 + g + ((e >> 1) << 3);
                int col = wc * 64 + nt * 8 + 2 * t + (e & 1);
                sAcc[row * DS + col] += f2acc[mt * 8 + nt][e];
            }
    __syncthreads();

    // S6: store (+ b2), back to (b, d, H, W)
    for (int id = tid; id < 4096; id += 256) {
        int dd = id >> 4, w1r = (id >> 1) & 7, half = id & 1;
        int t0 = w1r * 8 + half * 4;
        float bb2 = pb2[dd];
        float4 o;
        o.x = sAcc[(t0 + 0) * DS + dd] + bb2;
        o.y = sAcc[(t0 + 1) * DS + dd] + bb2;
        o.z = sAcc[(t0 + 2) * DS + dd] + bb2;
        o.w = sAcc[(t0 + 3) * DS + dd] + bb2;
        *(float4*)(outp + base_g + dd * 65536 + w1r * 256 + half * 4) = o;
    }
}

extern "C" void kernel_launch(void* const* d_in, const int* in_sizes, int n_in,
                              void* d_out, int out_size) {
    cudaFuncSetAttribute(block_attn_kernel,
                         cudaFuncAttributeMaxDynamicSharedMemorySize, SMEM_BYTES);
    block_attn_kernel<<<2048, 256, SMEM_BYTES>>>(
        (const float*)d_in[0], (const float*)d_in[1], (const float*)d_in[2],
        (const float*)d_in[3], (const float*)d_in[4], (const float*)d_in[5],
        (const float*)d_in[6], (const float*)d_in[7], (const float*)d_in[8],
        (const float*)d_in[9], (const float*)d_in[10], (const float*)d_in[11],
        (const float*)d_in[12], (const float*)d_in[13], (float*)d_out);
}